// round 1
// baseline (speedup 1.0000x reference)
#include <cuda_runtime.h>

#define NB   8
#define SEQ  2048
#define ED   1024
#define HD   64

__device__ float g_q[NB * SEQ * HD];
__device__ float g_k[NB * SEQ * HD];
__device__ float g_v[NB * SEQ * HD];

// ---------------------------------------------------------------------------
// QKV projection: q/k/v[b,s,h] = sum_e x[b,s,e] * W{q,k,v}[h,e] + b{q,k,v}[h]
// Grid: 256 CTAs (64 rows each), 256 threads (16x16, 4x4 micro-tile).
// Shared operands stored transposed [e][row]/[e][h] -> contiguous float4 LDS.
// ---------------------------------------------------------------------------
__global__ __launch_bounds__(256, 1)
void qkv_kernel(const float* __restrict__ x,
                const float* __restrict__ Wq, const float* __restrict__ bq,
                const float* __restrict__ Wk, const float* __restrict__ bk,
                const float* __restrict__ Wv, const float* __restrict__ bv)
{
    __shared__ float xT [32][64];   // [e][row]
    __shared__ float wT0[32][64];   // [e][h]
    __shared__ float wT1[32][64];
    __shared__ float wT2[32][64];

    const int t  = threadIdx.x;
    const int ty = t >> 4;          // 0..15
    const int tx = t & 15;          // 0..15
    const int rowBase = blockIdx.x * 64;

    float acc0[4][4], acc1[4][4], acc2[4][4];
    #pragma unroll
    for (int i = 0; i < 4; i++)
        #pragma unroll
        for (int j = 0; j < 4; j++) { acc0[i][j] = 0.f; acc1[i][j] = 0.f; acc2[i][j] = 0.f; }

    const int lrow = t & 63;        // loader row (x-row or W-h-row)
    const int lec0 = t >> 6;        // 0..3

    for (int e0 = 0; e0 < ED; e0 += 32) {
        __syncthreads();
        #pragma unroll
        for (int it = 0; it < 2; it++) {
            int ec = lec0 + it * 4;             // 0..7 -> e offsets 0..31
            const size_t go = (size_t)e0 + ec * 4;
            float4 v4;
            v4 = *(const float4*)(x  + (size_t)(rowBase + lrow) * ED + go);
            xT [ec*4+0][lrow] = v4.x; xT [ec*4+1][lrow] = v4.y;
            xT [ec*4+2][lrow] = v4.z; xT [ec*4+3][lrow] = v4.w;
            v4 = *(const float4*)(Wq + (size_t)lrow * ED + go);
            wT0[ec*4+0][lrow] = v4.x; wT0[ec*4+1][lrow] = v4.y;
            wT0[ec*4+2][lrow] = v4.z; wT0[ec*4+3][lrow] = v4.w;
            v4 = *(const float4*)(Wk + (size_t)lrow * ED + go);
            wT1[ec*4+0][lrow] = v4.x; wT1[ec*4+1][lrow] = v4.y;
            wT1[ec*4+2][lrow] = v4.z; wT1[ec*4+3][lrow] = v4.w;
            v4 = *(const float4*)(Wv + (size_t)lrow * ED + go);
            wT2[ec*4+0][lrow] = v4.x; wT2[ec*4+1][lrow] = v4.y;
            wT2[ec*4+2][lrow] = v4.z; wT2[ec*4+3][lrow] = v4.w;
        }
        __syncthreads();

        #pragma unroll 8
        for (int e = 0; e < 32; e++) {
            float xr[4], w0r[4], w1r[4], w2r[4];
            *(float4*)xr  = *(const float4*)&xT [e][ty * 4];
            *(float4*)w0r = *(const float4*)&wT0[e][tx * 4];
            *(float4*)w1r = *(const float4*)&wT1[e][tx * 4];
            *(float4*)w2r = *(const float4*)&wT2[e][tx * 4];
            #pragma unroll
            for (int i = 0; i < 4; i++)
                #pragma unroll
                for (int j = 0; j < 4; j++) {
                    acc0[i][j] += xr[i] * w0r[j];
                    acc1[i][j] += xr[i] * w1r[j];
                    acc2[i][j] += xr[i] * w2r[j];
                }
        }
    }

    float bq4[4], bk4[4], bv4[4];
    *(float4*)bq4 = *(const float4*)(bq + tx * 4);
    *(float4*)bk4 = *(const float4*)(bk + tx * 4);
    *(float4*)bv4 = *(const float4*)(bv + tx * 4);

    #pragma unroll
    for (int i = 0; i < 4; i++) {
        const size_t o = (size_t)(rowBase + ty * 4 + i) * HD + tx * 4;
        float4 r;
        r.x = acc0[i][0] + bq4[0]; r.y = acc0[i][1] + bq4[1];
        r.z = acc0[i][2] + bq4[2]; r.w = acc0[i][3] + bq4[3];
        *(float4*)(g_q + o) = r;
        r.x = acc1[i][0] + bk4[0]; r.y = acc1[i][1] + bk4[1];
        r.z = acc1[i][2] + bk4[2]; r.w = acc1[i][3] + bk4[3];
        *(float4*)(g_k + o) = r;
        r.x = acc2[i][0] + bv4[0]; r.y = acc2[i][1] + bv4[1];
        r.z = acc2[i][2] + bv4[2]; r.w = acc2[i][3] + bv4[3];
        *(float4*)(g_v + o) = r;
    }
}

// ---------------------------------------------------------------------------
// Causal flash attention. BQ = BK = 64, online softmax.
// Grid: (16 pairs, 8 batches). Each CTA handles q-tiles {p, 31-p}:
// work = (p+1) + (32-p) = 33 k-tiles -> perfectly balanced CTAs.
// smem: qT[h][q], kT[h][k] (aliased as ps[q][k] after scores), vs[k][h] = 48KB.
// ---------------------------------------------------------------------------
__global__ __launch_bounds__(256, 1)
void attn_kernel(float* __restrict__ out)
{
    __shared__ float qT  [64][64];   // [h][q-row]
    __shared__ float kTps[64][64];   // phase 1: kT[h][k-col]; phase 2: ps[q-row][k]
    __shared__ float vs  [64][64];   // [k-row][h]

    const int t  = threadIdx.x;
    const int ty = t >> 4;           // 0..15 : q-row group
    const int tx = t & 15;           // 0..15 : col group (k for S, h for O)
    const int b  = blockIdx.y;
    const size_t bOff = (size_t)b * SEQ * HD;

    const int lrow = t & 63;
    const int lc0  = t >> 6;
    const int vrow0 = t >> 4;        // 0..15
    const int vc4   = t & 15;

    for (int pass = 0; pass < 2; pass++) {
        const int qt = (pass == 0) ? blockIdx.x : 31 - blockIdx.x;
        const int qbase = qt * 64;

        // load qT (transposed); visibility guaranteed by the post-load sync below
        #pragma unroll
        for (int it = 0; it < 4; it++) {
            int hc = lc0 + it * 4;
            float4 v4 = *(const float4*)(g_q + bOff + (size_t)(qbase + lrow) * HD + hc * 4);
            qT[hc*4+0][lrow] = v4.x; qT[hc*4+1][lrow] = v4.y;
            qT[hc*4+2][lrow] = v4.z; qT[hc*4+3][lrow] = v4.w;
        }

        float m_i[4], l_i[4], o[4][4];
        #pragma unroll
        for (int i = 0; i < 4; i++) {
            m_i[i] = -1e30f; l_i[i] = 0.f;
            #pragma unroll
            for (int j = 0; j < 4; j++) o[i][j] = 0.f;
        }

        for (int kt = 0; kt <= qt; kt++) {
            const int kbase = kt * 64;
            __syncthreads();   // (A) prev PV done before overwriting kTps/vs
            // kT: transposed load of K tile
            #pragma unroll
            for (int it = 0; it < 4; it++) {
                int hc = lc0 + it * 4;
                float4 v4 = *(const float4*)(g_k + bOff + (size_t)(kbase + lrow) * HD + hc * 4);
                kTps[hc*4+0][lrow] = v4.x; kTps[hc*4+1][lrow] = v4.y;
                kTps[hc*4+2][lrow] = v4.z; kTps[hc*4+3][lrow] = v4.w;
            }
            // V tile: direct coalesced copy
            #pragma unroll
            for (int it = 0; it < 4; it++) {
                int vr = vrow0 + it * 16;
                *(float4*)&vs[vr][vc4 * 4] =
                    *(const float4*)(g_v + bOff + (size_t)(kbase + vr) * HD + vc4 * 4);
            }
            __syncthreads();   // (B) tiles visible

            // S = Q K^T   (4x4 micro-tile, h-vectorized)
            float s[4][4];
            #pragma unroll
            for (int i = 0; i < 4; i++)
                #pragma unroll
                for (int j = 0; j < 4; j++) s[i][j] = 0.f;
            #pragma unroll 8
            for (int h = 0; h < 64; h++) {
                float qr[4], kr[4];
                *(float4*)qr = *(const float4*)&qT  [h][ty * 4];
                *(float4*)kr = *(const float4*)&kTps[h][tx * 4];
                #pragma unroll
                for (int i = 0; i < 4; i++)
                    #pragma unroll
                    for (int j = 0; j < 4; j++) s[i][j] += qr[i] * kr[j];
            }
            __syncthreads();   // (C) all kT reads done before ps overwrite

            // scale + causal mask (only diagonal tile can violate causality)
            const float scale = 0.125f;   // 1/sqrt(64)
            if (kt == qt) {
                #pragma unroll
                for (int i = 0; i < 4; i++)
                    #pragma unroll
                    for (int j = 0; j < 4; j++) {
                        float v = s[i][j] * scale;
                        if (kbase + tx * 4 + j > qbase + ty * 4 + i) v = -1e30f;
                        s[i][j] = v;
                    }
            } else {
                #pragma unroll
                for (int i = 0; i < 4; i++)
                    #pragma unroll
                    for (int j = 0; j < 4; j++) s[i][j] *= scale;
            }

            // online softmax (row spread over the 16 tx-lanes of a half-warp)
            #pragma unroll
            for (int i = 0; i < 4; i++) {
                float rmax = fmaxf(fmaxf(s[i][0], s[i][1]), fmaxf(s[i][2], s[i][3]));
                #pragma unroll
                for (int off = 8; off > 0; off >>= 1)
                    rmax = fmaxf(rmax, __shfl_xor_sync(0xffffffffu, rmax, off));
                float mnew  = fmaxf(m_i[i], rmax);
                float alpha = __expf(m_i[i] - mnew);
                m_i[i] = mnew;
                float rsum = 0.f;
                #pragma unroll
                for (int j = 0; j < 4; j++) {
                    float p = __expf(s[i][j] - mnew);
                    s[i][j] = p;
                    rsum += p;
                }
                #pragma unroll
                for (int off = 8; off > 0; off >>= 1)
                    rsum += __shfl_xor_sync(0xffffffffu, rsum, off);
                l_i[i] = l_i[i] * alpha + rsum;
                #pragma unroll
                for (int j = 0; j < 4; j++) o[i][j] *= alpha;
            }

            // ps[q][k] (reuses kT buffer), contiguous float4 stores
            #pragma unroll
            for (int i = 0; i < 4; i++)
                *(float4*)&kTps[ty * 4 + i][tx * 4] = *(float4*)&s[i][0];
            __syncthreads();   // (D) ps visible

            // O += P V
            #pragma unroll 2
            for (int kk = 0; kk < 64; kk += 4) {
                float pr[4][4];
                #pragma unroll
                for (int i = 0; i < 4; i++)
                    *(float4*)pr[i] = *(const float4*)&kTps[ty * 4 + i][kk];
                #pragma unroll
                for (int u = 0; u < 4; u++) {
                    float vr[4];
                    *(float4*)vr = *(const float4*)&vs[kk + u][tx * 4];
                    #pragma unroll
                    for (int i = 0; i < 4; i++)
                        #pragma unroll
                        for (int j = 0; j < 4; j++)
                            o[i][j] += pr[i][u] * vr[j];
                }
            }
        }

        // normalize + write
        #pragma unroll
        for (int i = 0; i < 4; i++) {
            const float inv = 1.f / l_i[i];
            float4 r;
            r.x = o[i][0] * inv; r.y = o[i][1] * inv;
            r.z = o[i][2] * inv; r.w = o[i][3] * inv;
            *(float4*)(out + bOff + (size_t)(qbase + ty * 4 + i) * HD + tx * 4) = r;
        }
    }
}

// ---------------------------------------------------------------------------
extern "C" void kernel_launch(void* const* d_in, const int* in_sizes, int n_in,
                              void* d_out, int out_size)
{
    const float* x  = (const float*)d_in[0];
    const float* Wq = (const float*)d_in[1];
    const float* bq = (const float*)d_in[2];
    const float* Wk = (const float*)d_in[3];
    const float* bk = (const float*)d_in[4];
    const float* Wv = (const float*)d_in[5];
    const float* bv = (const float*)d_in[6];
    float* out = (float*)d_out;

    qkv_kernel<<<(NB * SEQ) / 64, 256>>>(x, Wq, bq, Wk, bk, Wv, bv);
    attn_kernel<<<dim3(16, NB), 256>>>(out);
}

// round 2
// speedup vs baseline: 1.5512x; 1.5512x over previous
#include <cuda_runtime.h>
#include <cstdint>

#define NB   8
#define SEQ  2048
#define ED   1024
#define HD   64

__device__ float g_q[NB * SEQ * HD];
__device__ float g_k[NB * SEQ * HD];
__device__ float g_v[NB * SEQ * HD];

__device__ __forceinline__ uint32_t f2tf32(float f) {
    uint32_t r;
    asm("cvt.rna.tf32.f32 %0, %1;" : "=r"(r) : "f"(f));
    return r;
}

__device__ __forceinline__ void mma_tf32(float* d, const uint32_t* a, const uint32_t* b) {
    asm("mma.sync.aligned.m16n8k8.row.col.f32.tf32.tf32.f32 "
        "{%0,%1,%2,%3}, {%4,%5,%6,%7}, {%8,%9}, {%0,%1,%2,%3};"
        : "+f"(d[0]), "+f"(d[1]), "+f"(d[2]), "+f"(d[3])
        : "r"(a[0]), "r"(a[1]), "r"(a[2]), "r"(a[3]), "r"(b[0]), "r"(b[1]));
}

// ---------------------------------------------------------------------------
// QKV projection via split-tf32 MMA (hi*hi + hi*lo + lo*hi ~ fp32 accuracy).
// BM=128, N=192 (q|k|v), K-chunks of 32. Grid 128 CTAs, 256 threads (8 warps:
// 2m x 4n, warp tile 64 x 48).
// ---------------------------------------------------------------------------
__global__ __launch_bounds__(256, 1)
void qkv_kernel(const float* __restrict__ x,
                const float* __restrict__ Wq, const float* __restrict__ bq,
                const float* __restrict__ Wk, const float* __restrict__ bk,
                const float* __restrict__ Wv, const float* __restrict__ bv)
{
    __shared__ float xs[128][36];
    __shared__ float ws[192][36];

    const int t    = threadIdx.x;
    const int lane = t & 31;
    const int wid  = t >> 5;
    const int wm   = wid & 1;      // 0..1 : 64-row half
    const int wn   = wid >> 1;     // 0..3 : 48-col slice
    const int rowBase = blockIdx.x * 128;
    const int gq = lane >> 2;      // group id 0..7
    const int tg = lane & 3;       // thread in group 0..3

    float acc[4][6][4];
    #pragma unroll
    for (int mi = 0; mi < 4; mi++)
        #pragma unroll
        for (int ni = 0; ni < 6; ni++)
            #pragma unroll
            for (int j = 0; j < 4; j++) acc[mi][ni][j] = 0.f;

    for (int e0 = 0; e0 < ED; e0 += 32) {
        __syncthreads();
        #pragma unroll
        for (int k = 0; k < 4; k++) {
            int f = t + k * 256;
            int r = f >> 3, c4 = f & 7;
            *(float4*)&xs[r][c4 * 4] =
                *(const float4*)(x + (size_t)(rowBase + r) * ED + e0 + c4 * 4);
        }
        #pragma unroll
        for (int k = 0; k < 6; k++) {
            int f = t + k * 256;
            int r = f >> 3, c4 = f & 7;
            const float* src = (r < 64)  ? Wq + (size_t)r * ED
                             : (r < 128) ? Wk + (size_t)(r - 64) * ED
                                         : Wv + (size_t)(r - 128) * ED;
            *(float4*)&ws[r][c4 * 4] = *(const float4*)(src + e0 + c4 * 4);
        }
        __syncthreads();

        #pragma unroll
        for (int kk = 0; kk < 4; kk++) {
            const int c0 = kk * 8 + tg;
            uint32_t ah[4][4], al[4][4];
            #pragma unroll
            for (int mi = 0; mi < 4; mi++) {
                int r0 = wm * 64 + mi * 16 + gq;
                float f0 = xs[r0][c0],     f1 = xs[r0 + 8][c0];
                float f2 = xs[r0][c0 + 4], f3 = xs[r0 + 8][c0 + 4];
                ah[mi][0] = f2tf32(f0); al[mi][0] = f2tf32(f0 - __uint_as_float(ah[mi][0]));
                ah[mi][1] = f2tf32(f1); al[mi][1] = f2tf32(f1 - __uint_as_float(ah[mi][1]));
                ah[mi][2] = f2tf32(f2); al[mi][2] = f2tf32(f2 - __uint_as_float(ah[mi][2]));
                ah[mi][3] = f2tf32(f3); al[mi][3] = f2tf32(f3 - __uint_as_float(ah[mi][3]));
            }
            uint32_t bh[6][2], bl[6][2];
            #pragma unroll
            for (int ni = 0; ni < 6; ni++) {
                int n0 = wn * 48 + ni * 8 + gq;
                float f0 = ws[n0][c0], f1 = ws[n0][c0 + 4];
                bh[ni][0] = f2tf32(f0); bl[ni][0] = f2tf32(f0 - __uint_as_float(bh[ni][0]));
                bh[ni][1] = f2tf32(f1); bl[ni][1] = f2tf32(f1 - __uint_as_float(bh[ni][1]));
            }
            #pragma unroll
            for (int mi = 0; mi < 4; mi++)
                #pragma unroll
                for (int ni = 0; ni < 6; ni++) mma_tf32(acc[mi][ni], ah[mi], bh[ni]);
            #pragma unroll
            for (int mi = 0; mi < 4; mi++)
                #pragma unroll
                for (int ni = 0; ni < 6; ni++) mma_tf32(acc[mi][ni], ah[mi], bl[ni]);
            #pragma unroll
            for (int mi = 0; mi < 4; mi++)
                #pragma unroll
                for (int ni = 0; ni < 6; ni++) mma_tf32(acc[mi][ni], al[mi], bh[ni]);
        }
    }

    #pragma unroll
    for (int ni = 0; ni < 6; ni++) {
        const int gc0 = wn * 48 + ni * 8;
        const int wi  = gc0 >> 6;
        const int h0  = (gc0 & 63) + tg * 2;
        float* outp      = (wi == 0) ? g_q : (wi == 1) ? g_k : g_v;
        const float* bp  = (wi == 0) ? bq  : (wi == 1) ? bk  : bv;
        const float b0 = bp[h0], b1 = bp[h0 + 1];
        #pragma unroll
        for (int mi = 0; mi < 4; mi++) {
            int r = rowBase + wm * 64 + mi * 16 + gq;
            float2 v0 = make_float2(acc[mi][ni][0] + b0, acc[mi][ni][1] + b1);
            *(float2*)(outp + (size_t)r * HD + h0) = v0;
            float2 v1 = make_float2(acc[mi][ni][2] + b0, acc[mi][ni][3] + b1);
            *(float2*)(outp + (size_t)(r + 8) * HD + h0) = v1;
        }
    }
}

// ---------------------------------------------------------------------------
// Causal flash attention via tf32 MMA. BQ=BK=64, 4 warps (16 q-rows each),
// online softmax warp-local. S uses split-tf32 (3 mma), PV plain tf32.
// Grid (16 pairs, 8 b); each CTA does q-tiles {p, 31-p}: 33 k-tiles, balanced.
// ---------------------------------------------------------------------------
__global__ __launch_bounds__(128, 1)
void attn_kernel(float* __restrict__ out)
{
    __shared__ float ks[64][68];
    __shared__ float vs[64][68];

    const int t    = threadIdx.x;
    const int lane = t & 31;
    const int w    = t >> 5;       // 0..3
    const int gq   = lane >> 2;
    const int tg   = lane & 3;
    const int b    = blockIdx.y;
    const size_t bOff = (size_t)b * SEQ * HD;

    for (int pass = 0; pass < 2; pass++) {
        const int qt = pass ? (31 - blockIdx.x) : blockIdx.x;
        const int qbase = qt * 64;

        // Q fragments resident in registers (split hi/lo), loaded straight from gmem
        uint32_t qh[8][4], ql[8][4];
        {
            const float* qp = g_q + bOff;
            const int r0 = qbase + w * 16 + gq;
            #pragma unroll
            for (int k8 = 0; k8 < 8; k8++) {
                int c0 = k8 * 8 + tg;
                float f0 = qp[(size_t)r0 * HD + c0];
                float f1 = qp[(size_t)(r0 + 8) * HD + c0];
                float f2 = qp[(size_t)r0 * HD + c0 + 4];
                float f3 = qp[(size_t)(r0 + 8) * HD + c0 + 4];
                qh[k8][0] = f2tf32(f0); ql[k8][0] = f2tf32(f0 - __uint_as_float(qh[k8][0]));
                qh[k8][1] = f2tf32(f1); ql[k8][1] = f2tf32(f1 - __uint_as_float(qh[k8][1]));
                qh[k8][2] = f2tf32(f2); ql[k8][2] = f2tf32(f2 - __uint_as_float(qh[k8][2]));
                qh[k8][3] = f2tf32(f3); ql[k8][3] = f2tf32(f3 - __uint_as_float(qh[k8][3]));
            }
        }

        float m0 = -1e30f, m1 = -1e30f, l0 = 0.f, l1 = 0.f;
        float O[8][4];
        #pragma unroll
        for (int nh = 0; nh < 8; nh++)
            #pragma unroll
            for (int j = 0; j < 4; j++) O[nh][j] = 0.f;

        for (int kt = 0; kt <= qt; kt++) {
            const int kbase = kt * 64;
            __syncthreads();
            #pragma unroll
            for (int k = 0; k < 8; k++) {
                int f = t + 128 * k;
                int r = f >> 4, c4 = f & 15;
                *(float4*)&ks[r][c4 * 4] =
                    *(const float4*)(g_k + bOff + (size_t)(kbase + r) * HD + c4 * 4);
                *(float4*)&vs[r][c4 * 4] =
                    *(const float4*)(g_v + bOff + (size_t)(kbase + r) * HD + c4 * 4);
            }
            __syncthreads();

            // ---- S = Q K^T (split-tf32) ----
            float s[8][4];
            #pragma unroll
            for (int nk = 0; nk < 8; nk++)
                #pragma unroll
                for (int j = 0; j < 4; j++) s[nk][j] = 0.f;

            #pragma unroll
            for (int k8 = 0; k8 < 8; k8++) {
                uint32_t bh[8][2], bl[8][2];
                #pragma unroll
                for (int nk = 0; nk < 8; nk++) {
                    float f0 = ks[nk * 8 + gq][k8 * 8 + tg];
                    float f1 = ks[nk * 8 + gq][k8 * 8 + tg + 4];
                    bh[nk][0] = f2tf32(f0); bl[nk][0] = f2tf32(f0 - __uint_as_float(bh[nk][0]));
                    bh[nk][1] = f2tf32(f1); bl[nk][1] = f2tf32(f1 - __uint_as_float(bh[nk][1]));
                }
                #pragma unroll
                for (int nk = 0; nk < 8; nk++) mma_tf32(s[nk], qh[k8], bh[nk]);
                #pragma unroll
                for (int nk = 0; nk < 8; nk++) mma_tf32(s[nk], qh[k8], bl[nk]);
                #pragma unroll
                for (int nk = 0; nk < 8; nk++) mma_tf32(s[nk], ql[k8], bh[nk]);
            }

            // ---- scale + causal mask + online softmax ----
            const float sc = 0.125f;   // 1/sqrt(64)
            if (kt == qt) {
                const int rl0 = w * 16 + gq;
                #pragma unroll
                for (int nk = 0; nk < 8; nk++) {
                    int cl = nk * 8 + tg * 2;
                    s[nk][0] = (cl     > rl0    ) ? -1e30f : s[nk][0] * sc;
                    s[nk][1] = (cl + 1 > rl0    ) ? -1e30f : s[nk][1] * sc;
                    s[nk][2] = (cl     > rl0 + 8) ? -1e30f : s[nk][2] * sc;
                    s[nk][3] = (cl + 1 > rl0 + 8) ? -1e30f : s[nk][3] * sc;
                }
            } else {
                #pragma unroll
                for (int nk = 0; nk < 8; nk++)
                    #pragma unroll
                    for (int j = 0; j < 4; j++) s[nk][j] *= sc;
            }

            float rm0 = -1e30f, rm1 = -1e30f;
            #pragma unroll
            for (int nk = 0; nk < 8; nk++) {
                rm0 = fmaxf(rm0, fmaxf(s[nk][0], s[nk][1]));
                rm1 = fmaxf(rm1, fmaxf(s[nk][2], s[nk][3]));
            }
            rm0 = fmaxf(rm0, __shfl_xor_sync(0xffffffffu, rm0, 1));
            rm0 = fmaxf(rm0, __shfl_xor_sync(0xffffffffu, rm0, 2));
            rm1 = fmaxf(rm1, __shfl_xor_sync(0xffffffffu, rm1, 1));
            rm1 = fmaxf(rm1, __shfl_xor_sync(0xffffffffu, rm1, 2));

            float mn0 = fmaxf(m0, rm0), mn1 = fmaxf(m1, rm1);
            float a0 = __expf(m0 - mn0), a1 = __expf(m1 - mn1);
            m0 = mn0; m1 = mn1;

            float rs0 = 0.f, rs1 = 0.f;
            #pragma unroll
            for (int nk = 0; nk < 8; nk++) {
                s[nk][0] = __expf(s[nk][0] - mn0); rs0 += s[nk][0];
                s[nk][1] = __expf(s[nk][1] - mn0); rs0 += s[nk][1];
                s[nk][2] = __expf(s[nk][2] - mn1); rs1 += s[nk][2];
                s[nk][3] = __expf(s[nk][3] - mn1); rs1 += s[nk][3];
            }
            rs0 += __shfl_xor_sync(0xffffffffu, rs0, 1);
            rs0 += __shfl_xor_sync(0xffffffffu, rs0, 2);
            rs1 += __shfl_xor_sync(0xffffffffu, rs1, 1);
            rs1 += __shfl_xor_sync(0xffffffffu, rs1, 2);
            l0 = l0 * a0 + rs0;
            l1 = l1 * a1 + rs1;
            #pragma unroll
            for (int nh = 0; nh < 8; nh++) {
                O[nh][0] *= a0; O[nh][1] *= a0;
                O[nh][2] *= a1; O[nh][3] *= a1;
            }

            // ---- O += P V (plain tf32, V rows permuted to match P's C-layout) ----
            #pragma unroll
            for (int t8 = 0; t8 < 8; t8++) {
                uint32_t pa[4];
                pa[0] = f2tf32(s[t8][0]);
                pa[1] = f2tf32(s[t8][2]);
                pa[2] = f2tf32(s[t8][1]);
                pa[3] = f2tf32(s[t8][3]);
                const int kc = t8 * 8 + tg * 2;
                #pragma unroll
                for (int nh = 0; nh < 8; nh++) {
                    const int hc = nh * 8 + gq;
                    uint32_t vb[2];
                    vb[0] = f2tf32(vs[kc][hc]);
                    vb[1] = f2tf32(vs[kc + 1][hc]);
                    mma_tf32(O[nh], pa, vb);
                }
            }
        }

        // ---- normalize + write ----
        const float inv0 = 1.f / l0, inv1 = 1.f / l1;
        const int r = qbase + w * 16 + gq;
        #pragma unroll
        for (int nh = 0; nh < 8; nh++) {
            const int h0 = nh * 8 + tg * 2;
            float2 v0 = make_float2(O[nh][0] * inv0, O[nh][1] * inv0);
            *(float2*)(out + bOff + (size_t)r * HD + h0) = v0;
            float2 v1 = make_float2(O[nh][2] * inv1, O[nh][3] * inv1);
            *(float2*)(out + bOff + (size_t)(r + 8) * HD + h0) = v1;
        }
    }
}

// ---------------------------------------------------------------------------
extern "C" void kernel_launch(void* const* d_in, const int* in_sizes, int n_in,
                              void* d_out, int out_size)
{
    const float* x  = (const float*)d_in[0];
    const float* Wq = (const float*)d_in[1];
    const float* bq = (const float*)d_in[2];
    const float* Wk = (const float*)d_in[3];
    const float* bk = (const float*)d_in[4];
    const float* Wv = (const float*)d_in[5];
    const float* bv = (const float*)d_in[6];
    float* out = (float*)d_out;

    qkv_kernel<<<(NB * SEQ) / 128, 256>>>(x, Wq, bq, Wk, bk, Wv, bv);
    attn_kernel<<<dim3(16, NB), 128>>>(out);
}

// round 3
// speedup vs baseline: 1.8185x; 1.1723x over previous
#include <cuda_runtime.h>
#include <cstdint>

#define NB   8
#define SEQ  2048
#define ED   1024
#define HD   64

__device__ float g_q[NB * SEQ * HD];
__device__ float g_k[NB * SEQ * HD];
__device__ float g_v[NB * SEQ * HD];

__device__ __forceinline__ uint32_t f2tf32(float f) {
    uint32_t r;
    asm("cvt.rna.tf32.f32 %0, %1;" : "=r"(r) : "f"(f));
    return r;
}

__device__ __forceinline__ void mma_tf32(float* d, const uint32_t* a, const uint32_t* b) {
    asm("mma.sync.aligned.m16n8k8.row.col.f32.tf32.tf32.f32 "
        "{%0,%1,%2,%3}, {%4,%5,%6,%7}, {%8,%9}, {%0,%1,%2,%3};"
        : "+f"(d[0]), "+f"(d[1]), "+f"(d[2]), "+f"(d[3])
        : "r"(a[0]), "r"(a[1]), "r"(a[2]), "r"(a[3]), "r"(b[0]), "r"(b[1]));
}

// ---------------------------------------------------------------------------
// QKV projection, split-tf32 (3-term, ~fp32 accuracy). BM=64, N=192, K-chunk 32.
// Grid 256 CTAs x 256 threads (8 warps: 2m x 4n, warp tile 32x48), 2 CTAs/SM.
// ---------------------------------------------------------------------------
__global__ __launch_bounds__(256, 2)
void qkv_kernel(const float* __restrict__ x,
                const float* __restrict__ Wq, const float* __restrict__ bq,
                const float* __restrict__ Wk, const float* __restrict__ bk,
                const float* __restrict__ Wv, const float* __restrict__ bv)
{
    __shared__ __align__(16) float xs[64][36];
    __shared__ __align__(16) float ws[192][36];

    const int t    = threadIdx.x;
    const int lane = t & 31;
    const int wid  = t >> 5;
    const int wm   = wid & 1;      // 0..1 : 32-row half
    const int wn   = wid >> 1;     // 0..3 : 48-col slice
    const int rowBase = blockIdx.x * 64;
    const int gq = lane >> 2;
    const int tg = lane & 3;

    float acc[2][6][4];
    #pragma unroll
    for (int mi = 0; mi < 2; mi++)
        #pragma unroll
        for (int ni = 0; ni < 6; ni++)
            #pragma unroll
            for (int j = 0; j < 4; j++) acc[mi][ni][j] = 0.f;

    for (int e0 = 0; e0 < ED; e0 += 32) {
        __syncthreads();
        #pragma unroll
        for (int k = 0; k < 2; k++) {
            int f = t + k * 256;
            int r = f >> 3, c4 = f & 7;
            *(float4*)&xs[r][c4 * 4] =
                *(const float4*)(x + (size_t)(rowBase + r) * ED + e0 + c4 * 4);
        }
        #pragma unroll
        for (int k = 0; k < 6; k++) {
            int f = t + k * 256;
            int r = f >> 3, c4 = f & 7;
            const float* src = (r < 64)  ? Wq + (size_t)r * ED
                             : (r < 128) ? Wk + (size_t)(r - 64) * ED
                                         : Wv + (size_t)(r - 128) * ED;
            *(float4*)&ws[r][c4 * 4] = *(const float4*)(src + e0 + c4 * 4);
        }
        __syncthreads();

        #pragma unroll
        for (int kk = 0; kk < 4; kk++) {
            const int c0 = kk * 8 + tg;
            uint32_t ah[2][4], al[2][4];
            #pragma unroll
            for (int mi = 0; mi < 2; mi++) {
                int r0 = wm * 32 + mi * 16 + gq;
                float f0 = xs[r0][c0],     f1 = xs[r0 + 8][c0];
                float f2 = xs[r0][c0 + 4], f3 = xs[r0 + 8][c0 + 4];
                ah[mi][0] = f2tf32(f0); al[mi][0] = f2tf32(f0 - __uint_as_float(ah[mi][0]));
                ah[mi][1] = f2tf32(f1); al[mi][1] = f2tf32(f1 - __uint_as_float(ah[mi][1]));
                ah[mi][2] = f2tf32(f2); al[mi][2] = f2tf32(f2 - __uint_as_float(ah[mi][2]));
                ah[mi][3] = f2tf32(f3); al[mi][3] = f2tf32(f3 - __uint_as_float(ah[mi][3]));
            }
            uint32_t bh[6][2], bl[6][2];
            #pragma unroll
            for (int ni = 0; ni < 6; ni++) {
                int n0 = wn * 48 + ni * 8 + gq;
                float f0 = ws[n0][c0], f1 = ws[n0][c0 + 4];
                bh[ni][0] = f2tf32(f0); bl[ni][0] = f2tf32(f0 - __uint_as_float(bh[ni][0]));
                bh[ni][1] = f2tf32(f1); bl[ni][1] = f2tf32(f1 - __uint_as_float(bh[ni][1]));
            }
            #pragma unroll
            for (int mi = 0; mi < 2; mi++)
                #pragma unroll
                for (int ni = 0; ni < 6; ni++) mma_tf32(acc[mi][ni], ah[mi], bh[ni]);
            #pragma unroll
            for (int mi = 0; mi < 2; mi++)
                #pragma unroll
                for (int ni = 0; ni < 6; ni++) mma_tf32(acc[mi][ni], ah[mi], bl[ni]);
            #pragma unroll
            for (int mi = 0; mi < 2; mi++)
                #pragma unroll
                for (int ni = 0; ni < 6; ni++) mma_tf32(acc[mi][ni], al[mi], bh[ni]);
        }
    }

    #pragma unroll
    for (int ni = 0; ni < 6; ni++) {
        const int gc0 = wn * 48 + ni * 8;
        const int wi  = gc0 >> 6;
        const int h0  = (gc0 & 63) + tg * 2;
        float* outp      = (wi == 0) ? g_q : (wi == 1) ? g_k : g_v;
        const float* bp  = (wi == 0) ? bq  : (wi == 1) ? bk  : bv;
        const float b0 = bp[h0], b1 = bp[h0 + 1];
        #pragma unroll
        for (int mi = 0; mi < 2; mi++) {
            int r = rowBase + wm * 32 + mi * 16 + gq;
            float2 v0 = make_float2(acc[mi][ni][0] + b0, acc[mi][ni][1] + b1);
            *(float2*)(outp + (size_t)r * HD + h0) = v0;
            float2 v1 = make_float2(acc[mi][ni][2] + b0, acc[mi][ni][3] + b1);
            *(float2*)(outp + (size_t)(r + 8) * HD + h0) = v1;
        }
    }
}

// ---------------------------------------------------------------------------
// Causal flash attention, tf32 MMA. BQ=64, 8 warps in 2 groups: group g owns
// 32-row k-tiles with index 2*iter+g (iter=0..qt) -> equal work, independent
// online softmax, merged analytically at the end via smem.
// Grid (16 pairs, 8 b); q-tiles {p, 31-p} per CTA (33 iters, balanced).
// V is stored in smem pre-converted to tf32. S = qh*kh + ql*kh (2 MMAs).
// ---------------------------------------------------------------------------
__global__ __launch_bounds__(256, 1)
void attn_kernel(float* __restrict__ out)
{
    __shared__ __align__(16) float    ks [2][32][68];
    __shared__ __align__(16) uint32_t vst[2][32][68];

    const int t    = threadIdx.x;
    const int lane = t & 31;
    const int w    = t >> 5;       // 0..7
    const int g    = w >> 2;       // warp-group 0/1
    const int wg   = w & 3;        // warp within group
    const int gq   = lane >> 2;
    const int tg   = lane & 3;
    const int tl   = t & 127;      // thread id within group
    const int b    = blockIdx.y;
    const size_t bOff = (size_t)b * SEQ * HD;

    float* obuf = &ks[0][0][0];            // merge overlay [64][68]
    float* mlb  = (float*)&vst[0][0][0];   // merge overlay m,l per row

    for (int pass = 0; pass < 2; pass++) {
        const int qt = pass ? (31 - blockIdx.x) : blockIdx.x;
        const int qbase = qt * 64;
        const int r0l = wg * 16 + gq;       // local q-row (0..63), +8 for second

        // Q fragments in registers (split hi/lo)
        uint32_t qh[8][4], ql[8][4];
        {
            const float* qp = g_q + bOff;
            const int r0 = qbase + r0l;
            #pragma unroll
            for (int k8 = 0; k8 < 8; k8++) {
                int c0 = k8 * 8 + tg;
                float f0 = qp[(size_t)r0 * HD + c0];
                float f1 = qp[(size_t)(r0 + 8) * HD + c0];
                float f2 = qp[(size_t)r0 * HD + c0 + 4];
                float f3 = qp[(size_t)(r0 + 8) * HD + c0 + 4];
                qh[k8][0] = f2tf32(f0); ql[k8][0] = f2tf32(f0 - __uint_as_float(qh[k8][0]));
                qh[k8][1] = f2tf32(f1); ql[k8][1] = f2tf32(f1 - __uint_as_float(qh[k8][1]));
                qh[k8][2] = f2tf32(f2); ql[k8][2] = f2tf32(f2 - __uint_as_float(qh[k8][2]));
                qh[k8][3] = f2tf32(f3); ql[k8][3] = f2tf32(f3 - __uint_as_float(qh[k8][3]));
            }
        }

        float m0 = -1e30f, m1 = -1e30f, l0 = 0.f, l1 = 0.f;
        float O[8][4];
        #pragma unroll
        for (int nh = 0; nh < 8; nh++)
            #pragma unroll
            for (int j = 0; j < 4; j++) O[nh][j] = 0.f;

        for (int iter = 0; iter <= qt; iter++) {
            const int kbase = (2 * iter + g) * 32;
            __syncthreads();
            // group loads its own 32-row K/V tile; V converted to tf32 here
            #pragma unroll
            for (int k = 0; k < 4; k++) {
                int f = tl + 128 * k;
                int r = f >> 4, c4 = f & 15;
                *(float4*)&ks[g][r][c4 * 4] =
                    *(const float4*)(g_k + bOff + (size_t)(kbase + r) * HD + c4 * 4);
                float4 v4 = *(const float4*)(g_v + bOff + (size_t)(kbase + r) * HD + c4 * 4);
                uint4 u4;
                u4.x = f2tf32(v4.x); u4.y = f2tf32(v4.y);
                u4.z = f2tf32(v4.z); u4.w = f2tf32(v4.w);
                *(uint4*)&vst[g][r][c4 * 4] = u4;
            }
            __syncthreads();

            // ---- S = Q K^T  (qh*kh + ql*kh) ----
            float s[4][4];
            #pragma unroll
            for (int nk = 0; nk < 4; nk++)
                #pragma unroll
                for (int j = 0; j < 4; j++) s[nk][j] = 0.f;

            #pragma unroll
            for (int k8 = 0; k8 < 8; k8++) {
                uint32_t bh[4][2];
                #pragma unroll
                for (int nk = 0; nk < 4; nk++) {
                    bh[nk][0] = f2tf32(ks[g][nk * 8 + gq][k8 * 8 + tg]);
                    bh[nk][1] = f2tf32(ks[g][nk * 8 + gq][k8 * 8 + tg + 4]);
                }
                #pragma unroll
                for (int nk = 0; nk < 4; nk++) mma_tf32(s[nk], qh[k8], bh[nk]);
                #pragma unroll
                for (int nk = 0; nk < 4; nk++) mma_tf32(s[nk], ql[k8], bh[nk]);
            }

            // ---- scale + causal mask ----
            const float sc = 0.125f;
            if (iter == qt) {
                const int row0 = qbase + r0l, row1 = row0 + 8;
                #pragma unroll
                for (int nk = 0; nk < 4; nk++) {
                    int c = kbase + nk * 8 + tg * 2;
                    s[nk][0] = (c     > row0) ? -1e30f : s[nk][0] * sc;
                    s[nk][1] = (c + 1 > row0) ? -1e30f : s[nk][1] * sc;
                    s[nk][2] = (c     > row1) ? -1e30f : s[nk][2] * sc;
                    s[nk][3] = (c + 1 > row1) ? -1e30f : s[nk][3] * sc;
                }
            } else {
                #pragma unroll
                for (int nk = 0; nk < 4; nk++)
                    #pragma unroll
                    for (int j = 0; j < 4; j++) s[nk][j] *= sc;
            }

            // ---- online softmax (rows spread over tg lanes) ----
            float rm0 = -1e30f, rm1 = -1e30f;
            #pragma unroll
            for (int nk = 0; nk < 4; nk++) {
                rm0 = fmaxf(rm0, fmaxf(s[nk][0], s[nk][1]));
                rm1 = fmaxf(rm1, fmaxf(s[nk][2], s[nk][3]));
            }
            rm0 = fmaxf(rm0, __shfl_xor_sync(0xffffffffu, rm0, 1));
            rm0 = fmaxf(rm0, __shfl_xor_sync(0xffffffffu, rm0, 2));
            rm1 = fmaxf(rm1, __shfl_xor_sync(0xffffffffu, rm1, 1));
            rm1 = fmaxf(rm1, __shfl_xor_sync(0xffffffffu, rm1, 2));

            float mn0 = fmaxf(m0, rm0), mn1 = fmaxf(m1, rm1);
            float a0 = __expf(m0 - mn0), a1 = __expf(m1 - mn1);
            m0 = mn0; m1 = mn1;

            float rs0 = 0.f, rs1 = 0.f;
            #pragma unroll
            for (int nk = 0; nk < 4; nk++) {
                s[nk][0] = __expf(s[nk][0] - mn0); rs0 += s[nk][0];
                s[nk][1] = __expf(s[nk][1] - mn0); rs0 += s[nk][1];
                s[nk][2] = __expf(s[nk][2] - mn1); rs1 += s[nk][2];
                s[nk][3] = __expf(s[nk][3] - mn1); rs1 += s[nk][3];
            }
            rs0 += __shfl_xor_sync(0xffffffffu, rs0, 1);
            rs0 += __shfl_xor_sync(0xffffffffu, rs0, 2);
            rs1 += __shfl_xor_sync(0xffffffffu, rs1, 1);
            rs1 += __shfl_xor_sync(0xffffffffu, rs1, 2);
            l0 = l0 * a0 + rs0;
            l1 = l1 * a1 + rs1;
            #pragma unroll
            for (int nh = 0; nh < 8; nh++) {
                O[nh][0] *= a0; O[nh][1] *= a0;
                O[nh][2] *= a1; O[nh][3] *= a1;
            }

            // ---- O += P V  (V pre-tf32; rows permuted for A-frag layout) ----
            #pragma unroll
            for (int t8 = 0; t8 < 4; t8++) {
                uint32_t pa[4];
                pa[0] = f2tf32(s[t8][0]);
                pa[1] = f2tf32(s[t8][2]);
                pa[2] = f2tf32(s[t8][1]);
                pa[3] = f2tf32(s[t8][3]);
                const int kc = t8 * 8 + tg * 2;
                #pragma unroll
                for (int nh = 0; nh < 8; nh++) {
                    const int hc = nh * 8 + gq;
                    uint32_t vb[2];
                    vb[0] = vst[g][kc][hc];
                    vb[1] = vst[g][kc + 1][hc];
                    mma_tf32(O[nh], pa, vb);
                }
            }
        }

        // ---- merge the two groups ----
        __syncthreads();
        if (g == 1) {
            mlb[r0l * 2]           = m0;
            mlb[r0l * 2 + 1]       = l0;
            mlb[(r0l + 8) * 2]     = m1;
            mlb[(r0l + 8) * 2 + 1] = l1;
            #pragma unroll
            for (int nh = 0; nh < 8; nh++) {
                int c = nh * 8 + tg * 2;
                *(float2*)&obuf[r0l * 68 + c]       = make_float2(O[nh][0], O[nh][1]);
                *(float2*)&obuf[(r0l + 8) * 68 + c] = make_float2(O[nh][2], O[nh][3]);
            }
        }
        __syncthreads();
        if (g == 0) {
            float mb0 = mlb[r0l * 2],       lb0 = mlb[r0l * 2 + 1];
            float mb1 = mlb[(r0l + 8) * 2], lb1 = mlb[(r0l + 8) * 2 + 1];
            float mm0 = fmaxf(m0, mb0), mm1 = fmaxf(m1, mb1);
            float ea0 = __expf(m0 - mm0),  eb0 = __expf(mb0 - mm0);
            float ea1 = __expf(m1 - mm1),  eb1 = __expf(mb1 - mm1);
            float inv0 = 1.f / (ea0 * l0 + eb0 * lb0);
            float inv1 = 1.f / (ea1 * l1 + eb1 * lb1);
            const int r = qbase + r0l;
            #pragma unroll
            for (int nh = 0; nh < 8; nh++) {
                int c = nh * 8 + tg * 2;
                float2 ob0 = *(float2*)&obuf[r0l * 68 + c];
                float2 ob1 = *(float2*)&obuf[(r0l + 8) * 68 + c];
                float2 v0 = make_float2((ea0 * O[nh][0] + eb0 * ob0.x) * inv0,
                                        (ea0 * O[nh][1] + eb0 * ob0.y) * inv0);
                float2 v1 = make_float2((ea1 * O[nh][2] + eb1 * ob1.x) * inv1,
                                        (ea1 * O[nh][3] + eb1 * ob1.y) * inv1);
                *(float2*)(out + bOff + (size_t)r * HD + c)       = v0;
                *(float2*)(out + bOff + (size_t)(r + 8) * HD + c) = v1;
            }
        }
    }
}

// ---------------------------------------------------------------------------
extern "C" void kernel_launch(void* const* d_in, const int* in_sizes, int n_in,
                              void* d_out, int out_size)
{
    const float* x  = (const float*)d_in[0];
    const float* Wq = (const float*)d_in[1];
    const float* bq = (const float*)d_in[2];
    const float* Wk = (const float*)d_in[3];
    const float* bk = (const float*)d_in[4];
    const float* Wv = (const float*)d_in[5];
    const float* bv = (const float*)d_in[6];
    float* out = (float*)d_out;

    qkv_kernel<<<(NB * SEQ) / 64, 256>>>(x, Wq, bq, Wk, bk, Wv, bv);
    attn_kernel<<<dim3(16, NB), 256>>>(out);
}

// round 5
// speedup vs baseline: 2.4787x; 1.3631x over previous
#include <cuda_runtime.h>
#include <cuda_bf16.h>
#include <cstdint>

#define NB   8
#define SEQ  2048
#define ED   1024
#define HD   64

__device__ float g_q[NB * SEQ * HD];
__device__ float g_k[NB * SEQ * HD];
__device__ float g_v[NB * SEQ * HD];
__device__ uint32_t g_whp[192 * 512];   // W hi, bf16 pairs packed
__device__ uint32_t g_wlp[192 * 512];   // W lo

// ---------------- helpers ----------------
__device__ __forceinline__ uint32_t f2tf32(float f) {
    uint32_t r;
    asm("cvt.rna.tf32.f32 %0, %1;" : "=r"(r) : "f"(f));
    return r;
}
__device__ __forceinline__ void mma_tf32(float* d, const uint32_t* a, const uint32_t* b) {
    asm("mma.sync.aligned.m16n8k8.row.col.f32.tf32.tf32.f32 "
        "{%0,%1,%2,%3}, {%4,%5,%6,%7}, {%8,%9}, {%0,%1,%2,%3};"
        : "+f"(d[0]), "+f"(d[1]), "+f"(d[2]), "+f"(d[3])
        : "r"(a[0]), "r"(a[1]), "r"(a[2]), "r"(a[3]), "r"(b[0]), "r"(b[1]));
}
__device__ __forceinline__ void mma_bf16(float* d, const uint32_t* a, const uint32_t* b) {
    asm("mma.sync.aligned.m16n8k16.row.col.f32.bf16.bf16.f32 "
        "{%0,%1,%2,%3}, {%4,%5,%6,%7}, {%8,%9}, {%0,%1,%2,%3};"
        : "+f"(d[0]), "+f"(d[1]), "+f"(d[2]), "+f"(d[3])
        : "r"(a[0]), "r"(a[1]), "r"(a[2]), "r"(a[3]), "r"(b[0]), "r"(b[1]));
}
// split (a,b) into packed bf16 hi pair + lo pair (lo = residual)
__device__ __forceinline__ void split2(float a, float b, uint32_t& hi, uint32_t& lo) {
    __nv_bfloat162 h2 = __floats2bfloat162_rn(a, b);
    float ar = a - __bfloat162float(h2.x);
    float br = b - __bfloat162float(h2.y);
    __nv_bfloat162 l2 = __floats2bfloat162_rn(ar, br);
    hi = *(uint32_t*)&h2;
    lo = *(uint32_t*)&l2;
}

// ---------------------------------------------------------------------------
// Prep: split W (q|k|v stacked, 192 x 1024) into packed bf16 hi/lo pairs.
// ---------------------------------------------------------------------------
__global__ void prep_w(const float* __restrict__ Wq, const float* __restrict__ Wk,
                       const float* __restrict__ Wv)
{
    int idx = blockIdx.x * 256 + threadIdx.x;
    if (idx >= 192 * 512) return;
    int row = idx >> 9;
    int pc  = idx & 511;
    const float* src = (row < 64)  ? Wq + (size_t)row * ED
                     : (row < 128) ? Wk + (size_t)(row - 64) * ED
                                   : Wv + (size_t)(row - 128) * ED;
    float a = src[pc * 2], b = src[pc * 2 + 1];
    uint32_t h, l;
    split2(a, b, h, l);
    g_whp[idx] = h;
    g_wlp[idx] = l;
}

// ---------------------------------------------------------------------------
// QKV via bf16 m16n8k16, 3-term split (xh*wh + xh*wl + xl*wh ~ fp32 accuracy).
// BM=64, N=192, K-chunk 32 (2 ksteps). 256 CTAs x 8 warps (2m x 4n), 2 CTAs/SM.
// smem stride 20 u32 -> conflict-free fragment loads.
// ---------------------------------------------------------------------------
__global__ __launch_bounds__(256, 2)
void qkv_kernel(const float* __restrict__ x,
                const float* __restrict__ bq, const float* __restrict__ bk,
                const float* __restrict__ bv)
{
    __shared__ uint32_t xs_h[64][20],  xs_l[64][20];
    __shared__ uint32_t ws_h[192][20], ws_l[192][20];

    const int t    = threadIdx.x;
    const int lane = t & 31;
    const int wid  = t >> 5;
    const int wm   = wid & 1;
    const int wn   = wid >> 1;
    const int gq   = lane >> 2;
    const int tg   = lane & 3;
    const size_t rowBase = (size_t)blockIdx.x * 64;

    float acc[2][6][4];
    #pragma unroll
    for (int mi = 0; mi < 2; mi++)
        #pragma unroll
        for (int ni = 0; ni < 6; ni++)
            #pragma unroll
            for (int j = 0; j < 4; j++) acc[mi][ni][j] = 0.f;

    const int xr = t >> 2;          // x loader row
    const int xc = (t & 3) * 8;     // x loader col (floats)

    for (int ch = 0; ch < 32; ch++) {
        __syncthreads();
        // x tile: 8 floats/thread -> split + pack
        {
            const float* xp = x + (rowBase + xr) * ED + ch * 32 + xc;
            float4 f0 = *(const float4*)xp;
            float4 f1 = *(const float4*)(xp + 4);
            uint4 hv, lv;
            split2(f0.x, f0.y, hv.x, lv.x);
            split2(f0.z, f0.w, hv.y, lv.y);
            split2(f1.x, f1.y, hv.z, lv.z);
            split2(f1.z, f1.w, hv.w, lv.w);
            *(uint4*)&xs_h[xr][(t & 3) * 4] = hv;
            *(uint4*)&xs_l[xr][(t & 3) * 4] = lv;
        }
        // W tile: pre-packed, 3 uint4 per thread per array
        #pragma unroll
        for (int i = 0; i < 3; i++) {
            int slot = t + i * 256;
            int r = slot >> 2, c4 = (slot & 3) * 4;
            *(uint4*)&ws_h[r][c4] = *(const uint4*)&g_whp[r * 512 + ch * 16 + c4];
            *(uint4*)&ws_l[r][c4] = *(const uint4*)&g_wlp[r * 512 + ch * 16 + c4];
        }
        __syncthreads();

        #pragma unroll
        for (int kk = 0; kk < 2; kk++) {
            const int c0 = kk * 8 + tg;
            uint32_t ah[2][4], al[2][4];
            #pragma unroll
            for (int mi = 0; mi < 2; mi++) {
                int r0 = wm * 32 + mi * 16 + gq;
                ah[mi][0] = xs_h[r0][c0];     ah[mi][1] = xs_h[r0 + 8][c0];
                ah[mi][2] = xs_h[r0][c0 + 4]; ah[mi][3] = xs_h[r0 + 8][c0 + 4];
                al[mi][0] = xs_l[r0][c0];     al[mi][1] = xs_l[r0 + 8][c0];
                al[mi][2] = xs_l[r0][c0 + 4]; al[mi][3] = xs_l[r0 + 8][c0 + 4];
            }
            uint32_t bh[6][2], bl[6][2];
            #pragma unroll
            for (int ni = 0; ni < 6; ni++) {
                int n0 = wn * 48 + ni * 8 + gq;
                bh[ni][0] = ws_h[n0][c0]; bh[ni][1] = ws_h[n0][c0 + 4];
                bl[ni][0] = ws_l[n0][c0]; bl[ni][1] = ws_l[n0][c0 + 4];
            }
            #pragma unroll
            for (int mi = 0; mi < 2; mi++)
                #pragma unroll
                for (int ni = 0; ni < 6; ni++) mma_bf16(acc[mi][ni], ah[mi], bh[ni]);
            #pragma unroll
            for (int mi = 0; mi < 2; mi++)
                #pragma unroll
                for (int ni = 0; ni < 6; ni++) mma_bf16(acc[mi][ni], ah[mi], bl[ni]);
            #pragma unroll
            for (int mi = 0; mi < 2; mi++)
                #pragma unroll
                for (int ni = 0; ni < 6; ni++) mma_bf16(acc[mi][ni], al[mi], bh[ni]);
        }
    }

    #pragma unroll
    for (int ni = 0; ni < 6; ni++) {
        const int gc0 = wn * 48 + ni * 8;
        const int wi  = gc0 >> 6;
        const int h0  = (gc0 & 63) + tg * 2;
        float* outp      = (wi == 0) ? g_q : (wi == 1) ? g_k : g_v;
        const float* bp  = (wi == 0) ? bq  : (wi == 1) ? bk  : bv;
        const float b0 = bp[h0], b1 = bp[h0 + 1];
        #pragma unroll
        for (int mi = 0; mi < 2; mi++) {
            size_t r = rowBase + wm * 32 + mi * 16 + gq;
            float2 v0 = make_float2(acc[mi][ni][0] + b0, acc[mi][ni][1] + b1);
            *(float2*)(outp + r * HD + h0) = v0;
            float2 v1 = make_float2(acc[mi][ni][2] + b0, acc[mi][ni][3] + b1);
            *(float2*)(outp + (r + 8) * HD + h0) = v1;
        }
    }
}

// ---------------------------------------------------------------------------
// Causal flash attention, tf32 MMA. 8 warps in 2 independent groups (group g
// owns 32-row k-tiles 2*iter+g), group-local named barriers, register
// prefetch of the next K/V tile, smem tiles pre-converted to tf32.
// Grid (16 pairs, 8 b); q-tiles {p, 31-p} per CTA (33 iters, balanced).
// ---------------------------------------------------------------------------
#define GROUP_BAR(gid) asm volatile("bar.sync %0, 128;" :: "r"((gid) + 1) : "memory")

__global__ __launch_bounds__(256, 1)
void attn_kernel(float* __restrict__ out)
{
    __shared__ __align__(16) uint32_t kst[2][32][68];
    __shared__ __align__(16) uint32_t vst[2][32][68];

    const int t    = threadIdx.x;
    const int lane = t & 31;
    const int w    = t >> 5;
    const int g    = w >> 2;
    const int wg   = w & 3;
    const int gq   = lane >> 2;
    const int tg   = lane & 3;
    const int tl   = t & 127;
    const int b    = blockIdx.y;
    const size_t bOff = (size_t)b * SEQ * HD;

    float* obuf = (float*)&kst[0][0][0];
    float* mlb  = (float*)&vst[0][0][0];

    const int ldr = tl >> 4;        // loader row base within quarter
    const int ldc = tl & 15;        // loader col quad

    for (int pass = 0; pass < 2; pass++) {
        __syncthreads();            // protect merge overlays across passes
        const int qt = pass ? (31 - blockIdx.x) : blockIdx.x;
        const int qbase = qt * 64;
        const int r0l = wg * 16 + gq;

        // Q fragments in registers (split hi/lo tf32)
        uint32_t qh[8][4], ql[8][4];
        {
            const float* qp = g_q + bOff;
            const int r0 = qbase + r0l;
            #pragma unroll
            for (int k8 = 0; k8 < 8; k8++) {
                int c0 = k8 * 8 + tg;
                float f0 = qp[(size_t)r0 * HD + c0];
                float f1 = qp[(size_t)(r0 + 8) * HD + c0];
                float f2 = qp[(size_t)r0 * HD + c0 + 4];
                float f3 = qp[(size_t)(r0 + 8) * HD + c0 + 4];
                qh[k8][0] = f2tf32(f0); ql[k8][0] = f2tf32(f0 - __uint_as_float(qh[k8][0]));
                qh[k8][1] = f2tf32(f1); ql[k8][1] = f2tf32(f1 - __uint_as_float(qh[k8][1]));
                qh[k8][2] = f2tf32(f2); ql[k8][2] = f2tf32(f2 - __uint_as_float(qh[k8][2]));
                qh[k8][3] = f2tf32(f3); ql[k8][3] = f2tf32(f3 - __uint_as_float(qh[k8][3]));
            }
        }

        float m0 = -1e30f, m1 = -1e30f, l0 = 0.f, l1 = 0.f;
        float O[8][4];
        #pragma unroll
        for (int nh = 0; nh < 8; nh++)
            #pragma unroll
            for (int j = 0; j < 4; j++) O[nh][j] = 0.f;

        // prologue: prefetch iter-0 tile into registers
        float4 kr[4], vr[4];
        {
            const int kbase = g * 32;
            #pragma unroll
            for (int k = 0; k < 4; k++) {
                int r = ldr + k * 8;
                kr[k] = *(const float4*)(g_k + bOff + (size_t)(kbase + r) * HD + ldc * 4);
                vr[k] = *(const float4*)(g_v + bOff + (size_t)(kbase + r) * HD + ldc * 4);
            }
        }

        for (int iter = 0; iter <= qt; iter++) {
            const int kbase = (2 * iter + g) * 32;
            GROUP_BAR(g);   // all group warps done reading previous tile
            #pragma unroll
            for (int k = 0; k < 4; k++) {
                int r = ldr + k * 8;
                uint4 ku, vu;
                ku.x = f2tf32(kr[k].x); ku.y = f2tf32(kr[k].y);
                ku.z = f2tf32(kr[k].z); ku.w = f2tf32(kr[k].w);
                vu.x = f2tf32(vr[k].x); vu.y = f2tf32(vr[k].y);
                vu.z = f2tf32(vr[k].z); vu.w = f2tf32(vr[k].w);
                *(uint4*)&kst[g][r][ldc * 4] = ku;
                *(uint4*)&vst[g][r][ldc * 4] = vu;
            }
            if (iter < qt) {
                const int kb2 = (2 * (iter + 1) + g) * 32;
                #pragma unroll
                for (int k = 0; k < 4; k++) {
                    int r = ldr + k * 8;
                    kr[k] = *(const float4*)(g_k + bOff + (size_t)(kb2 + r) * HD + ldc * 4);
                    vr[k] = *(const float4*)(g_v + bOff + (size_t)(kb2 + r) * HD + ldc * 4);
                }
            }
            GROUP_BAR(g);   // tile visible to the group

            // ---- S = Q K^T  (qh*kh + ql*kh) ----
            float s[4][4];
            #pragma unroll
            for (int nk = 0; nk < 4; nk++)
                #pragma unroll
                for (int j = 0; j < 4; j++) s[nk][j] = 0.f;

            #pragma unroll
            for (int k8 = 0; k8 < 8; k8++) {
                uint32_t bh[4][2];
                #pragma unroll
                for (int nk = 0; nk < 4; nk++) {
                    bh[nk][0] = kst[g][nk * 8 + gq][k8 * 8 + tg];
                    bh[nk][1] = kst[g][nk * 8 + gq][k8 * 8 + tg + 4];
                }
                #pragma unroll
                for (int nk = 0; nk < 4; nk++) mma_tf32(s[nk], qh[k8], bh[nk]);
                #pragma unroll
                for (int nk = 0; nk < 4; nk++) mma_tf32(s[nk], ql[k8], bh[nk]);
            }

            // ---- scale + causal mask ----
            const float sc = 0.125f;
            if (iter == qt) {
                const int row0 = qbase + r0l, row1 = row0 + 8;
                #pragma unroll
                for (int nk = 0; nk < 4; nk++) {
                    int c = kbase + nk * 8 + tg * 2;
                    s[nk][0] = (c     > row0) ? -1e30f : s[nk][0] * sc;
                    s[nk][1] = (c + 1 > row0) ? -1e30f : s[nk][1] * sc;
                    s[nk][2] = (c     > row1) ? -1e30f : s[nk][2] * sc;
                    s[nk][3] = (c + 1 > row1) ? -1e30f : s[nk][3] * sc;
                }
            } else {
                #pragma unroll
                for (int nk = 0; nk < 4; nk++)
                    #pragma unroll
                    for (int j = 0; j < 4; j++) s[nk][j] *= sc;
            }

            // ---- online softmax ----
            float rm0 = -1e30f, rm1 = -1e30f;
            #pragma unroll
            for (int nk = 0; nk < 4; nk++) {
                rm0 = fmaxf(rm0, fmaxf(s[nk][0], s[nk][1]));
                rm1 = fmaxf(rm1, fmaxf(s[nk][2], s[nk][3]));
            }
            rm0 = fmaxf(rm0, __shfl_xor_sync(0xffffffffu, rm0, 1));
            rm0 = fmaxf(rm0, __shfl_xor_sync(0xffffffffu, rm0, 2));
            rm1 = fmaxf(rm1, __shfl_xor_sync(0xffffffffu, rm1, 1));
            rm1 = fmaxf(rm1, __shfl_xor_sync(0xffffffffu, rm1, 2));

            float mn0 = fmaxf(m0, rm0), mn1 = fmaxf(m1, rm1);
            float a0 = __expf(m0 - mn0), a1 = __expf(m1 - mn1);
            m0 = mn0; m1 = mn1;

            float rs0 = 0.f, rs1 = 0.f;
            #pragma unroll
            for (int nk = 0; nk < 4; nk++) {
                s[nk][0] = __expf(s[nk][0] - mn0); rs0 += s[nk][0];
                s[nk][1] = __expf(s[nk][1] - mn0); rs0 += s[nk][1];
                s[nk][2] = __expf(s[nk][2] - mn1); rs1 += s[nk][2];
                s[nk][3] = __expf(s[nk][3] - mn1); rs1 += s[nk][3];
            }
            rs0 += __shfl_xor_sync(0xffffffffu, rs0, 1);
            rs0 += __shfl_xor_sync(0xffffffffu, rs0, 2);
            rs1 += __shfl_xor_sync(0xffffffffu, rs1, 1);
            rs1 += __shfl_xor_sync(0xffffffffu, rs1, 2);
            l0 = l0 * a0 + rs0;
            l1 = l1 * a1 + rs1;
            #pragma unroll
            for (int nh = 0; nh < 8; nh++) {
                O[nh][0] *= a0; O[nh][1] *= a0;
                O[nh][2] *= a1; O[nh][3] *= a1;
            }

            // ---- O += P V ----
            #pragma unroll
            for (int t8 = 0; t8 < 4; t8++) {
                uint32_t pa[4];
                pa[0] = f2tf32(s[t8][0]);
                pa[1] = f2tf32(s[t8][2]);
                pa[2] = f2tf32(s[t8][1]);
                pa[3] = f2tf32(s[t8][3]);
                const int kc = t8 * 8 + tg * 2;
                #pragma unroll
                for (int nh = 0; nh < 8; nh++) {
                    const int hc = nh * 8 + gq;
                    uint32_t vb[2];
                    vb[0] = vst[g][kc][hc];
                    vb[1] = vst[g][kc + 1][hc];
                    mma_tf32(O[nh], pa, vb);
                }
            }
        }

        // ---- merge the two groups ----
        __syncthreads();
        if (g == 1) {
            mlb[r0l * 2]           = m0;
            mlb[r0l * 2 + 1]       = l0;
            mlb[(r0l + 8) * 2]     = m1;
            mlb[(r0l + 8) * 2 + 1] = l1;
            #pragma unroll
            for (int nh = 0; nh < 8; nh++) {
                int c = nh * 8 + tg * 2;
                *(float2*)&obuf[r0l * 68 + c]       = make_float2(O[nh][0], O[nh][1]);
                *(float2*)&obuf[(r0l + 8) * 68 + c] = make_float2(O[nh][2], O[nh][3]);
            }
        }
        __syncthreads();
        if (g == 0) {
            float mb0 = mlb[r0l * 2],       lb0 = mlb[r0l * 2 + 1];
            float mb1 = mlb[(r0l + 8) * 2], lb1 = mlb[(r0l + 8) * 2 + 1];
            float mm0 = fmaxf(m0, mb0), mm1 = fmaxf(m1, mb1);
            float ea0 = __expf(m0 - mm0),  eb0 = __expf(mb0 - mm0);
            float ea1 = __expf(m1 - mm1),  eb1 = __expf(mb1 - mm1);
            float inv0 = 1.f / (ea0 * l0 + eb0 * lb0);
            float inv1 = 1.f / (ea1 * l1 + eb1 * lb1);
            const int r = qbase + r0l;
            #pragma unroll
            for (int nh = 0; nh < 8; nh++) {
                int c = nh * 8 + tg * 2;
                float2 ob0 = *(float2*)&obuf[r0l * 68 + c];
                float2 ob1 = *(float2*)&obuf[(r0l + 8) * 68 + c];
                float2 v0 = make_float2((ea0 * O[nh][0] + eb0 * ob0.x) * inv0,
                                        (ea0 * O[nh][1] + eb0 * ob0.y) * inv0);
                float2 v1 = make_float2((ea1 * O[nh][2] + eb1 * ob1.x) * inv1,
                                        (ea1 * O[nh][3] + eb1 * ob1.y) * inv1);
                *(float2*)(out + bOff + (size_t)r * HD + c)       = v0;
                *(float2*)(out + bOff + (size_t)(r + 8) * HD + c) = v1;
            }
        }
    }
}

// ---------------------------------------------------------------------------
extern "C" void kernel_launch(void* const* d_in, const int* in_sizes, int n_in,
                              void* d_out, int out_size)
{
    const float* x  = (const float*)d_in[0];
    const float* Wq = (const float*)d_in[1];
    const float* bq = (const float*)d_in[2];
    const float* Wk = (const float*)d_in[3];
    const float* bk = (const float*)d_in[4];
    const float* Wv = (const float*)d_in[5];
    const float* bv = (const float*)d_in[6];
    float* out = (float*)d_out;

    prep_w<<<384, 256>>>(Wq, Wk, Wv);
    qkv_kernel<<<(NB * SEQ) / 64, 256>>>(x, bq, bk, bv);
    attn_kernel<<<dim3(16, NB), 256>>>(out);
}